// round 15
// baseline (speedup 1.0000x reference)
#include <cuda_runtime.h>

#define BB 4
#define CC 12
#define HH0 512
#define NBC (BB*CC)          // 48
#define NSCALES 5
#define TS 32
#define TIN 42               // TS + 10
#define SPITCH 43
#define HPITCH 33
#define NTHR 256
#define NBLK_REST 4080       // 3072+768+192+48

__device__ float g_x0[(size_t)NBC*HH0*HH0];
__device__ float g_px1[(size_t)NBC*256*256];
__device__ float g_py1[(size_t)NBC*256*256];
__device__ float g_px2[(size_t)NBC*128*128];
__device__ float g_py2[(size_t)NBC*128*128];
__device__ float g_px3[(size_t)NBC*64*64];
__device__ float g_py3[(size_t)NBC*64*64];
__device__ float g_px4[(size_t)NBC*32*32];
__device__ float g_py4[(size_t)NBC*32*32];
__device__ float g_ss[NSCALES*NBC];
__device__ float g_cs[NSCALES*NBC];
__device__ int   g_done = 0;

__device__ __forceinline__ const float* pool_x(int s) {
    switch (s) { case 1: return g_px1; case 2: return g_px2;
                 case 3: return g_px3; default: return g_px4; }
}
__device__ __forceinline__ const float* pool_y(int s) {
    switch (s) { case 1: return g_py1; case 2: return g_py2;
                 case 3: return g_py3; default: return g_py4; }
}

// ---------------------------------------------------------------------------
__global__ __launch_bounds__(256) void softmax_x0(const float* __restrict__ pred)
{
    if (blockIdx.x == 0 && threadIdx.x < NSCALES*NBC) {
        g_ss[threadIdx.x] = 0.f; g_cs[threadIdx.x] = 0.f;
    }
    const int HW = HH0*HH0;
    int p = blockIdx.x*blockDim.x + threadIdx.x;
    if (p >= BB*HW) return;
    int b  = p / HW;
    int hw = p - b*HW;
    const float* pp = pred + (size_t)b*CC*HW + hw;

    float v[CC];
    float mx = -1e30f;
#pragma unroll
    for (int c = 0; c < CC; c++) { v[c] = pp[(size_t)c*HW]; mx = fmaxf(mx, v[c]); }
    float s = 0.f;
#pragma unroll
    for (int c = 0; c < CC; c++) { v[c] = expf(v[c]-mx); s += v[c]; }
    float inv = 1.f/s;
    size_t base = (size_t)b*CC*HW + hw;
#pragma unroll
    for (int c = 0; c < CC; c++) g_x0[base + (size_t)c*HW] = v[c]*inv;
}

// ---------------------------------------------------------------------------
// Shared SSIM tile math (proven scalar body). S0: y one-hot, yy plane dropped.
template<bool S0>
__device__ __forceinline__ void ssim_tile_math(
    float (*sx)[SPITCH], float (*sy)[SPITCH],
    float* hb0, float* hb1, float* hb2, float* hb4, float* hb3,
    int Hs, int ty0, int tx0, int sidx, int bc, float* rss, float* rcs)
{
    constexpr float G[11] = {0.00102838f,0.00759870f,0.03600080f,0.10936070f,
                             0.21300560f,0.26601180f,0.21300560f,0.10936070f,
                             0.03600080f,0.00759870f,0.00102838f};
    const int OH = Hs - 10;
    int tid = threadIdx.x;

    // Stage 1: horizontal blur, strips of 4 cols. 336 tasks.
    for (int task = tid; task < TIN*8; task += NTHR) {
        int r  = task >> 3;
        int c0 = (task & 7) << 2;
        float a0[4]={0,0,0,0}, a1[4]={0,0,0,0}, a2[4]={0,0,0,0};
        float a3[4]={0,0,0,0}, a4[4]={0,0,0,0};
#pragma unroll
        for (int i = 0; i < 14; i++) {
            float x = sx[r][c0+i], y = sy[r][c0+i];
            float xx = x*x, xy = x*y;
            float yy = S0 ? 0.f : y*y;
#pragma unroll
            for (int j = 0; j < 4; j++) {
                int k = i - j;
                if (k >= 0 && k < 11) {
                    a0[j] = fmaf(G[k], x,  a0[j]);
                    a1[j] = fmaf(G[k], y,  a1[j]);
                    a2[j] = fmaf(G[k], xx, a2[j]);
                    if (!S0) a3[j] = fmaf(G[k], yy, a3[j]);
                    a4[j] = fmaf(G[k], xy, a4[j]);
                }
            }
        }
        int o = r*HPITCH + c0;
#pragma unroll
        for (int j = 0; j < 4; j++) {
            hb0[o+j]=a0[j]; hb1[o+j]=a1[j]; hb2[o+j]=a2[j]; hb4[o+j]=a4[j];
            if (!S0) hb3[o+j]=a3[j];
        }
    }
    __syncthreads();

    // Stage 2: vertical blur + SSIM, strips of 4 rows. 256 tasks.
    float lss = 0.f, lcs = 0.f;
    {
        int c  = tid & 31;
        int r0 = (tid >> 5) << 2;
        float m1[4]={0,0,0,0}, m2[4]={0,0,0,0}, e11[4]={0,0,0,0};
        float e22[4]={0,0,0,0}, e12[4]={0,0,0,0};
#pragma unroll
        for (int i = 0; i < 14; i++) {
            int o = (r0+i)*HPITCH + c;
            float v0 = hb0[o], v1 = hb1[o], v2 = hb2[o], v4 = hb4[o];
            float v3 = S0 ? 0.f : hb3[o];
#pragma unroll
            for (int j = 0; j < 4; j++) {
                int k = i - j;
                if (k >= 0 && k < 11) {
                    m1[j]  = fmaf(G[k], v0, m1[j]);
                    m2[j]  = fmaf(G[k], v1, m2[j]);
                    e11[j] = fmaf(G[k], v2, e11[j]);
                    if (!S0) e22[j] = fmaf(G[k], v3, e22[j]);
                    e12[j] = fmaf(G[k], v4, e12[j]);
                }
            }
        }
        int ow = tx0 + c;
#pragma unroll
        for (int j = 0; j < 4; j++) {
            int oh = ty0 + r0 + j;
            if (oh < OH && ow < OH) {
                float M1 = m1[j], M2 = m2[j];
                float E22 = S0 ? M2 : e22[j];
                float m11 = M1*M1, m22 = M2*M2, m12 = M1*M2;
                float v1 = e11[j] - m11, v2 = E22 - m22, cov = e12[j] - m12;
                float cs = __fdividef(2.f*cov + 0.0009f, v1 + v2 + 0.0009f);
                float sv = __fdividef(2.f*m12 + 0.0001f, m11 + m22 + 0.0001f) * cs;
                lss += sv; lcs += cs;
            }
        }
    }

#pragma unroll
    for (int o = 16; o; o >>= 1) {
        lss += __shfl_down_sync(0xffffffffu, lss, o);
        lcs += __shfl_down_sync(0xffffffffu, lcs, o);
    }
    if ((tid & 31) == 0) { rss[tid>>5] = lss; rcs[tid>>5] = lcs; }
    __syncthreads();
    if (tid == 0) {
        float ts = 0.f, tc = 0.f;
#pragma unroll
        for (int w = 0; w < NTHR/32; w++) { ts += rss[w]; tc += rcs[w]; }
        atomicAdd(&g_ss[sidx*NBC + bc], ts);
        atomicAdd(&g_cs[sidx*NBC + bc], tc);
    }
}

// ---------------------------------------------------------------------------
// Scale 0: one-hot y; L1 pool by all threads, L2-L4 staged inside warp 0.
// 6 blocks/SM forced (scalar body, 16+16 accumulators -> 42 regs feasible).
__global__ __launch_bounds__(NTHR, 6) void ssim_s0(const int* __restrict__ tgt)
{
    __shared__ float sx[TIN][SPITCH];
    __shared__ float sy[TIN][SPITCH];
    __shared__ float hb[4*TIN*HPITCH];
    __shared__ float s1x[16*17], s1y[16*17];
    __shared__ float s2x[8*9],  s2y[8*9];
    __shared__ float s3x[4*5],  s3y[4*5];
    __shared__ float rss[NTHR/32], rcs[NTHR/32];

    int bc  = blockIdx.z;
    int tid = threadIdx.x;
    int by = blockIdx.y, bx = blockIdx.x;
    int ty0 = by*TS, tx0 = bx*TS;
    const float* xp = g_x0 + (size_t)bc*HH0*HH0;
    const int*   tp = tgt  + (size_t)(bc/CC)*HH0*HH0;
    int cls = bc % CC;

    // Tile load with incremental (r,c): 256 = 6*TIN + 4.
    {
        int r = tid / TIN, c = tid - (tid / TIN)*TIN;
        for (int i = tid; i < TIN*TIN; i += NTHR) {
            int ih = ty0 + r, iw = tx0 + c;
            float xv = 0.f, yv = 0.f;
            if (ih < HH0 && iw < HH0) {
                int o = ih*HH0 + iw;
                xv = xp[o];
                yv = (tp[o] == cls) ? 1.f : 0.f;
            }
            sx[r][c] = xv; sy[r][c] = yv;
            r += 6; c += 4;
            if (c >= TIN) { c -= TIN; r += 1; }
        }
    }
    __syncthreads();

    // L1: 32x32 -> 16x16 (scale 1), all 256 threads.
    {
        float* xo = g_px1 + (size_t)bc*256*256;
        float* yo = g_py1 + (size_t)bc*256*256;
        int pr = tid >> 4, pc = tid & 15;
        int r = pr*2, c = pc*2;
        float px = (sx[r][c]+sx[r][c+1]+sx[r+1][c]+sx[r+1][c+1])*0.25f;
        float py = (sy[r][c]+sy[r][c+1]+sy[r+1][c]+sy[r+1][c+1])*0.25f;
        xo[(by*16+pr)*256 + (bx*16+pc)] = px;
        yo[(by*16+pr)*256 + (bx*16+pc)] = py;
        s1x[pr*17+pc] = px; s1y[pr*17+pc] = py;
    }
    __syncthreads();

    // Warp 0: staged L2 -> L3 -> L4, warp-local sync only.
    if (tid < 32) {
        float* xo2 = g_px2 + (size_t)bc*128*128;
        float* yo2 = g_py2 + (size_t)bc*128*128;
#pragma unroll
        for (int q = 0; q < 2; q++) {
            int t = tid + q*32;
            int pr = t >> 3, pc = t & 7;
            int o = (2*pr)*17 + 2*pc;
            float px = (s1x[o]+s1x[o+1]+s1x[o+17]+s1x[o+18])*0.25f;
            float py = (s1y[o]+s1y[o+1]+s1y[o+17]+s1y[o+18])*0.25f;
            xo2[(by*8+pr)*128 + (bx*8+pc)] = px;
            yo2[(by*8+pr)*128 + (bx*8+pc)] = py;
            s2x[pr*9+pc] = px; s2y[pr*9+pc] = py;
        }
        __syncwarp();
        if (tid < 16) {
            float* xo3 = g_px3 + (size_t)bc*64*64;
            float* yo3 = g_py3 + (size_t)bc*64*64;
            int pr = tid >> 2, pc = tid & 3;
            int o = (2*pr)*9 + 2*pc;
            float px = (s2x[o]+s2x[o+1]+s2x[o+9]+s2x[o+10])*0.25f;
            float py = (s2y[o]+s2y[o+1]+s2y[o+9]+s2y[o+10])*0.25f;
            xo3[(by*4+pr)*64 + (bx*4+pc)] = px;
            yo3[(by*4+pr)*64 + (bx*4+pc)] = py;
            s3x[pr*5+pc] = px; s3y[pr*5+pc] = py;
        }
        __syncwarp();
        if (tid < 4) {
            float* xo4 = g_px4 + (size_t)bc*32*32;
            float* yo4 = g_py4 + (size_t)bc*32*32;
            int pr = tid >> 1, pc = tid & 1;
            int o = (2*pr)*5 + 2*pc;
            xo4[(by*2+pr)*32 + (bx*2+pc)] = (s3x[o]+s3x[o+1]+s3x[o+5]+s3x[o+6])*0.25f;
            yo4[(by*2+pr)*32 + (bx*2+pc)] = (s3y[o]+s3y[o+1]+s3y[o+5]+s3y[o+6])*0.25f;
        }
        __syncwarp();
    }

    ssim_tile_math<true>(sx, sy, hb, hb + TIN*HPITCH, hb + 2*TIN*HPITCH,
                         hb + 3*TIN*HPITCH, nullptr,
                         HH0, ty0, tx0, 0, bc, rss, rcs);
}

// ---------------------------------------------------------------------------
// Scales 1..4 in one launch + fused last-block finalize.
__global__ __launch_bounds__(NTHR) void ssim_rest(float* __restrict__ out)
{
    __shared__ float sx[TIN][SPITCH];
    __shared__ float sy[TIN][SPITCH];
    __shared__ float hb[5*TIN*HPITCH];
    __shared__ float rss[NTHR/32], rcs[NTHR/32];
    __shared__ int s_last;
    __shared__ float sm[NBC];

    int idx = blockIdx.x;
    int s, bc, ty, tx;
    if (idx < 3072)      { s=1; bc=idx>>6; int t=idx&63; ty=t>>3; tx=t&7; }
    else if (idx < 3840) { s=2; int r=idx-3072; bc=r>>4; int t=r&15; ty=t>>2; tx=t&3; }
    else if (idx < 4032) { s=3; int r=idx-3840; bc=r>>2; int t=r&3;  ty=t>>1; tx=t&1; }
    else                 { s=4; bc=idx-4032; ty=0; tx=0; }

    int Hs = HH0 >> s;
    int tid = threadIdx.x;
    int ty0 = ty*TS, tx0 = tx*TS;
    const float* xp = pool_x(s) + (size_t)bc*Hs*Hs;
    const float* yp = pool_y(s) + (size_t)bc*Hs*Hs;

    {
        int r = tid / TIN, c = tid - (tid / TIN)*TIN;
        for (int i = tid; i < TIN*TIN; i += NTHR) {
            int ih = ty0 + r, iw = tx0 + c;
            float xv = 0.f, yv = 0.f;
            if (ih < Hs && iw < Hs) {
                int o = ih*Hs + iw;
                xv = xp[o]; yv = yp[o];
            }
            sx[r][c] = xv; sy[r][c] = yv;
            r += 6; c += 4;
            if (c >= TIN) { c -= TIN; r += 1; }
        }
    }
    __syncthreads();

    ssim_tile_math<false>(sx, sy, hb, hb + TIN*HPITCH, hb + 2*TIN*HPITCH,
                          hb + 3*TIN*HPITCH, hb + 4*TIN*HPITCH,
                          Hs, ty0, tx0, s, bc, rss, rcs);

    // Last-block finalize.
    if (tid == 0) {
        __threadfence();
        int old = atomicAdd(&g_done, 1);
        s_last = (old == NBLK_REST-1) ? 1 : 0;
    }
    __syncthreads();
    if (s_last) {
        if (tid == 0) g_done = 0;   // reset for next graph replay
        const float Wt[5]  = {0.0448f, 0.2856f, 0.3001f, 0.2363f, 0.1333f};
        const float cnt[5] = {502.f*502.f, 246.f*246.f, 118.f*118.f,
                              54.f*54.f, 22.f*22.f};
        if (tid < NBC) {
            float ms = 1.f;
#pragma unroll
            for (int sc = 0; sc < NSCALES; sc++) {
                float acc = (sc == NSCALES-1) ? __ldcg(&g_ss[sc*NBC + tid])
                                              : __ldcg(&g_cs[sc*NBC + tid]);
                float v = fmaxf(acc / cnt[sc], 0.f);
                ms *= powf(v, Wt[sc]);
            }
            sm[tid] = ms;
        }
        __syncthreads();
        if (tid == 0) {
            float a = 0.f;
#pragma unroll
            for (int i = 0; i < NBC; i++) a += sm[i];
            out[0] = 1.f - a / (float)NBC;
        }
    }
}

// ---------------------------------------------------------------------------
extern "C" void kernel_launch(void* const* d_in, const int* in_sizes, int n_in,
                              void* d_out, int out_size)
{
    const float* pred = (const float*)d_in[0];
    const int*   tgt  = (const int*)d_in[1];
    float*       out  = (float*)d_out;

    int np = BB*HH0*HH0;
    softmax_x0<<<(np + 255)/256, 256>>>(pred);

    { dim3 g(16, 16, NBC); ssim_s0<<<g, NTHR>>>(tgt); }
    ssim_rest<<<NBLK_REST, NTHR>>>(out);
}

// round 16
// speedup vs baseline: 1.0245x; 1.0245x over previous
#include <cuda_runtime.h>

#define BB 4
#define CC 12
#define HH0 512
#define NBC (BB*CC)          // 48
#define NSCALES 5
#define TS 32
#define TIN 42               // TS + 10
#define SPITCH 43
#define HPITCH 33            // hb pitch (float2 units for packed planes)
#define NTHR 256
#define NBLK_REST 4080       // 3072+768+192+48

__device__ float g_x0[(size_t)NBC*HH0*HH0];
__device__ float g_px1[(size_t)NBC*256*256];
__device__ float g_py1[(size_t)NBC*256*256];
__device__ float g_px2[(size_t)NBC*128*128];
__device__ float g_py2[(size_t)NBC*128*128];
__device__ float g_px3[(size_t)NBC*64*64];
__device__ float g_py3[(size_t)NBC*64*64];
__device__ float g_px4[(size_t)NBC*32*32];
__device__ float g_py4[(size_t)NBC*32*32];
__device__ float g_ss[NSCALES*NBC];
__device__ float g_cs[NSCALES*NBC];
__device__ int   g_done = 0;

__device__ __forceinline__ const float* pool_x(int s) {
    switch (s) { case 1: return g_px1; case 2: return g_px2;
                 case 3: return g_px3; default: return g_px4; }
}
__device__ __forceinline__ const float* pool_y(int s) {
    switch (s) { case 1: return g_py1; case 2: return g_py2;
                 case 3: return g_py3; default: return g_py4; }
}

// ---------------------------------------------------------------------------
__global__ __launch_bounds__(256) void softmax_x0(const float* __restrict__ pred)
{
    if (blockIdx.x == 0 && threadIdx.x < NSCALES*NBC) {
        g_ss[threadIdx.x] = 0.f; g_cs[threadIdx.x] = 0.f;
    }
    const int HW = HH0*HH0;
    int p = blockIdx.x*blockDim.x + threadIdx.x;
    if (p >= BB*HW) return;
    int b  = p / HW;
    int hw = p - b*HW;
    const float* pp = pred + (size_t)b*CC*HW + hw;

    float v[CC];
    float mx = -1e30f;
#pragma unroll
    for (int c = 0; c < CC; c++) { v[c] = pp[(size_t)c*HW]; mx = fmaxf(mx, v[c]); }
    float s = 0.f;
#pragma unroll
    for (int c = 0; c < CC; c++) { v[c] = expf(v[c]-mx); s += v[c]; }
    float inv = 1.f/s;
    size_t base = (size_t)b*CC*HW + hw;
#pragma unroll
    for (int c = 0; c < CC; c++) g_x0[base + (size_t)c*HW] = v[c]*inv;
}

// ---------------------------------------------------------------------------
// SSIM tile math, hb planes packed pairwise: hb01 = (conv x, conv y),
// hb24 = (conv x^2, conv xy); hb3 scalar = conv y^2 (only when !S0).
template<bool S0>
__device__ __forceinline__ void ssim_tile_math(
    float (*sx)[SPITCH], float (*sy)[SPITCH],
    float2* hb01, float2* hb24, float* hb3,
    int Hs, int ty0, int tx0, int sidx, int bc, float* rss, float* rcs)
{
    constexpr float G[11] = {0.00102838f,0.00759870f,0.03600080f,0.10936070f,
                             0.21300560f,0.26601180f,0.21300560f,0.10936070f,
                             0.03600080f,0.00759870f,0.00102838f};
    const int OH = Hs - 10;
    int tid = threadIdx.x;

    // Stage 1: horizontal blur, strips of 4 cols. 336 tasks.
    for (int task = tid; task < TIN*8; task += NTHR) {
        int r  = task >> 3;
        int c0 = (task & 7) << 2;
        float a0[4]={0,0,0,0}, a1[4]={0,0,0,0}, a2[4]={0,0,0,0};
        float a3[4]={0,0,0,0}, a4[4]={0,0,0,0};
#pragma unroll
        for (int i = 0; i < 14; i++) {
            float x = sx[r][c0+i], y = sy[r][c0+i];
            float xx = x*x, xy = x*y;
            float yy = S0 ? 0.f : y*y;
#pragma unroll
            for (int j = 0; j < 4; j++) {
                int k = i - j;
                if (k >= 0 && k < 11) {
                    a0[j] = fmaf(G[k], x,  a0[j]);
                    a1[j] = fmaf(G[k], y,  a1[j]);
                    a2[j] = fmaf(G[k], xx, a2[j]);
                    if (!S0) a3[j] = fmaf(G[k], yy, a3[j]);
                    a4[j] = fmaf(G[k], xy, a4[j]);
                }
            }
        }
        int o = r*HPITCH + c0;
#pragma unroll
        for (int j = 0; j < 4; j++) {
            hb01[o+j] = make_float2(a0[j], a1[j]);
            hb24[o+j] = make_float2(a2[j], a4[j]);
            if (!S0) hb3[o+j] = a3[j];
        }
    }
    __syncthreads();

    // Stage 2: vertical blur + SSIM, strips of 4 rows. 256 tasks.
    float lss = 0.f, lcs = 0.f;
    {
        int c  = tid & 31;
        int r0 = (tid >> 5) << 2;
        float m1[4]={0,0,0,0}, m2[4]={0,0,0,0}, e11[4]={0,0,0,0};
        float e22[4]={0,0,0,0}, e12[4]={0,0,0,0};
#pragma unroll
        for (int i = 0; i < 14; i++) {
            int o = (r0+i)*HPITCH + c;
            float2 v01 = hb01[o];
            float2 v24 = hb24[o];
            float v3 = S0 ? 0.f : hb3[o];
#pragma unroll
            for (int j = 0; j < 4; j++) {
                int k = i - j;
                if (k >= 0 && k < 11) {
                    m1[j]  = fmaf(G[k], v01.x, m1[j]);
                    m2[j]  = fmaf(G[k], v01.y, m2[j]);
                    e11[j] = fmaf(G[k], v24.x, e11[j]);
                    if (!S0) e22[j] = fmaf(G[k], v3, e22[j]);
                    e12[j] = fmaf(G[k], v24.y, e12[j]);
                }
            }
        }
        int ow = tx0 + c;
#pragma unroll
        for (int j = 0; j < 4; j++) {
            int oh = ty0 + r0 + j;
            if (oh < OH && ow < OH) {
                float M1 = m1[j], M2 = m2[j];
                float E22 = S0 ? M2 : e22[j];
                float m11 = M1*M1, m22 = M2*M2, m12 = M1*M2;
                float v1 = e11[j] - m11, v2 = E22 - m22, cov = e12[j] - m12;
                float cs = __fdividef(2.f*cov + 0.0009f, v1 + v2 + 0.0009f);
                float sv = __fdividef(2.f*m12 + 0.0001f, m11 + m22 + 0.0001f) * cs;
                lss += sv; lcs += cs;
            }
        }
    }

#pragma unroll
    for (int o = 16; o; o >>= 1) {
        lss += __shfl_down_sync(0xffffffffu, lss, o);
        lcs += __shfl_down_sync(0xffffffffu, lcs, o);
    }
    if ((tid & 31) == 0) { rss[tid>>5] = lss; rcs[tid>>5] = lcs; }
    __syncthreads();
    if (tid == 0) {
        float ts = 0.f, tc = 0.f;
#pragma unroll
        for (int w = 0; w < NTHR/32; w++) { ts += rss[w]; tc += rcs[w]; }
        atomicAdd(&g_ss[sidx*NBC + bc], ts);
        atomicAdd(&g_cs[sidx*NBC + bc], tc);
    }
}

// ---------------------------------------------------------------------------
// Scale 0: one-hot y; L1 pool by all threads, L2-L4 staged inside warp 0.
__global__ __launch_bounds__(NTHR) void ssim_s0(const int* __restrict__ tgt)
{
    __shared__ float sx[TIN][SPITCH];
    __shared__ float sy[TIN][SPITCH];
    __shared__ __align__(8) float2 hb01[TIN*HPITCH];
    __shared__ __align__(8) float2 hb24[TIN*HPITCH];
    __shared__ float s1x[16*17], s1y[16*17];
    __shared__ float s2x[8*9],  s2y[8*9];
    __shared__ float s3x[4*5],  s3y[4*5];
    __shared__ float rss[NTHR/32], rcs[NTHR/32];

    int bc  = blockIdx.z;
    int tid = threadIdx.x;
    int by = blockIdx.y, bx = blockIdx.x;
    int ty0 = by*TS, tx0 = bx*TS;
    const float* xp = g_x0 + (size_t)bc*HH0*HH0;
    const int*   tp = tgt  + (size_t)(bc/CC)*HH0*HH0;
    int cls = bc % CC;

    {
        int r = tid / TIN, c = tid - (tid / TIN)*TIN;
        for (int i = tid; i < TIN*TIN; i += NTHR) {
            int ih = ty0 + r, iw = tx0 + c;
            float xv = 0.f, yv = 0.f;
            if (ih < HH0 && iw < HH0) {
                int o = ih*HH0 + iw;
                xv = xp[o];
                yv = (tp[o] == cls) ? 1.f : 0.f;
            }
            sx[r][c] = xv; sy[r][c] = yv;
            r += 6; c += 4;
            if (c >= TIN) { c -= TIN; r += 1; }
        }
    }
    __syncthreads();

    // L1: 32x32 -> 16x16 (scale 1), all 256 threads.
    {
        float* xo = g_px1 + (size_t)bc*256*256;
        float* yo = g_py1 + (size_t)bc*256*256;
        int pr = tid >> 4, pc = tid & 15;
        int r = pr*2, c = pc*2;
        float px = (sx[r][c]+sx[r][c+1]+sx[r+1][c]+sx[r+1][c+1])*0.25f;
        float py = (sy[r][c]+sy[r][c+1]+sy[r+1][c]+sy[r+1][c+1])*0.25f;
        xo[(by*16+pr)*256 + (bx*16+pc)] = px;
        yo[(by*16+pr)*256 + (bx*16+pc)] = py;
        s1x[pr*17+pc] = px; s1y[pr*17+pc] = py;
    }
    __syncthreads();

    // Warp 0: staged L2 -> L3 -> L4, warp-local sync only.
    if (tid < 32) {
        float* xo2 = g_px2 + (size_t)bc*128*128;
        float* yo2 = g_py2 + (size_t)bc*128*128;
#pragma unroll
        for (int q = 0; q < 2; q++) {
            int t = tid + q*32;
            int pr = t >> 3, pc = t & 7;
            int o = (2*pr)*17 + 2*pc;
            float px = (s1x[o]+s1x[o+1]+s1x[o+17]+s1x[o+18])*0.25f;
            float py = (s1y[o]+s1y[o+1]+s1y[o+17]+s1y[o+18])*0.25f;
            xo2[(by*8+pr)*128 + (bx*8+pc)] = px;
            yo2[(by*8+pr)*128 + (bx*8+pc)] = py;
            s2x[pr*9+pc] = px; s2y[pr*9+pc] = py;
        }
        __syncwarp();
        if (tid < 16) {
            float* xo3 = g_px3 + (size_t)bc*64*64;
            float* yo3 = g_py3 + (size_t)bc*64*64;
            int pr = tid >> 2, pc = tid & 3;
            int o = (2*pr)*9 + 2*pc;
            float px = (s2x[o]+s2x[o+1]+s2x[o+9]+s2x[o+10])*0.25f;
            float py = (s2y[o]+s2y[o+1]+s2y[o+9]+s2y[o+10])*0.25f;
            xo3[(by*4+pr)*64 + (bx*4+pc)] = px;
            yo3[(by*4+pr)*64 + (bx*4+pc)] = py;
            s3x[pr*5+pc] = px; s3y[pr*5+pc] = py;
        }
        __syncwarp();
        if (tid < 4) {
            float* xo4 = g_px4 + (size_t)bc*32*32;
            float* yo4 = g_py4 + (size_t)bc*32*32;
            int pr = tid >> 1, pc = tid & 1;
            int o = (2*pr)*5 + 2*pc;
            xo4[(by*2+pr)*32 + (bx*2+pc)] = (s3x[o]+s3x[o+1]+s3x[o+5]+s3x[o+6])*0.25f;
            yo4[(by*2+pr)*32 + (bx*2+pc)] = (s3y[o]+s3y[o+1]+s3y[o+5]+s3y[o+6])*0.25f;
        }
        __syncwarp();
    }

    ssim_tile_math<true>(sx, sy, hb01, hb24, nullptr,
                         HH0, ty0, tx0, 0, bc, rss, rcs);
}

// ---------------------------------------------------------------------------
// Scales 1..4 in one launch + fused last-block finalize.
__global__ __launch_bounds__(NTHR) void ssim_rest(float* __restrict__ out)
{
    __shared__ float sx[TIN][SPITCH];
    __shared__ float sy[TIN][SPITCH];
    __shared__ __align__(8) float2 hb01[TIN*HPITCH];
    __shared__ __align__(8) float2 hb24[TIN*HPITCH];
    __shared__ float hb3[TIN*HPITCH];
    __shared__ float rss[NTHR/32], rcs[NTHR/32];
    __shared__ int s_last;
    __shared__ float sm[NBC];

    int idx = blockIdx.x;
    int s, bc, ty, tx;
    if (idx < 3072)      { s=1; bc=idx>>6; int t=idx&63; ty=t>>3; tx=t&7; }
    else if (idx < 3840) { s=2; int r=idx-3072; bc=r>>4; int t=r&15; ty=t>>2; tx=t&3; }
    else if (idx < 4032) { s=3; int r=idx-3840; bc=r>>2; int t=r&3;  ty=t>>1; tx=t&1; }
    else                 { s=4; bc=idx-4032; ty=0; tx=0; }

    int Hs = HH0 >> s;
    int tid = threadIdx.x;
    int ty0 = ty*TS, tx0 = tx*TS;
    const float* xp = pool_x(s) + (size_t)bc*Hs*Hs;
    const float* yp = pool_y(s) + (size_t)bc*Hs*Hs;

    {
        int r = tid / TIN, c = tid - (tid / TIN)*TIN;
        for (int i = tid; i < TIN*TIN; i += NTHR) {
            int ih = ty0 + r, iw = tx0 + c;
            float xv = 0.f, yv = 0.f;
            if (ih < Hs && iw < Hs) {
                int o = ih*Hs + iw;
                xv = xp[o]; yv = yp[o];
            }
            sx[r][c] = xv; sy[r][c] = yv;
            r += 6; c += 4;
            if (c >= TIN) { c -= TIN; r += 1; }
        }
    }
    __syncthreads();

    ssim_tile_math<false>(sx, sy, hb01, hb24, hb3,
                          Hs, ty0, tx0, s, bc, rss, rcs);

    // Last-block finalize.
    if (tid == 0) {
        __threadfence();
        int old = atomicAdd(&g_done, 1);
        s_last = (old == NBLK_REST-1) ? 1 : 0;
    }
    __syncthreads();
    if (s_last) {
        if (tid == 0) g_done = 0;   // reset for next graph replay
        const float Wt[5]  = {0.0448f, 0.2856f, 0.3001f, 0.2363f, 0.1333f};
        const float cnt[5] = {502.f*502.f, 246.f*246.f, 118.f*118.f,
                              54.f*54.f, 22.f*22.f};
        if (tid < NBC) {
            float ms = 1.f;
#pragma unroll
            for (int sc = 0; sc < NSCALES; sc++) {
                float acc = (sc == NSCALES-1) ? __ldcg(&g_ss[sc*NBC + tid])
                                              : __ldcg(&g_cs[sc*NBC + tid]);
                float v = fmaxf(acc / cnt[sc], 0.f);
                ms *= powf(v, Wt[sc]);
            }
            sm[tid] = ms;
        }
        __syncthreads();
        if (tid == 0) {
            float a = 0.f;
#pragma unroll
            for (int i = 0; i < NBC; i++) a += sm[i];
            out[0] = 1.f - a / (float)NBC;
        }
    }
}

// ---------------------------------------------------------------------------
extern "C" void kernel_launch(void* const* d_in, const int* in_sizes, int n_in,
                              void* d_out, int out_size)
{
    const float* pred = (const float*)d_in[0];
    const int*   tgt  = (const int*)d_in[1];
    float*       out  = (float*)d_out;

    int np = BB*HH0*HH0;
    softmax_x0<<<(np + 255)/256, 256>>>(pred);

    { dim3 g(16, 16, NBC); ssim_s0<<<g, NTHR>>>(tgt); }
    ssim_rest<<<NBLK_REST, NTHR>>>(out);
}